// round 8
// baseline (speedup 1.0000x reference)
#include <cuda_runtime.h>
#include <cstdint>
#include <cstddef>

#define T_STEPS 1024
#define BATCH   8
#define DIM     1024
#define NSLOTS  8
#define RANK    256
#define GROUP   16            // CTAs per slot group (= cluster size)
#define NCTAS   (NSLOTS*GROUP)
#define NTHR    512

// SMEM strides (floats). All are odd multiples of 4 floats (16B) =>
// 16B-aligned rows AND conflict-free LDS.128 column access.
#define SV_STRIDE  68          // V chunk: [256 r][64 d]   (17 float4, odd)
#define SU_STRIDE  260         // U chunk: [64 d][256 r]   (65 float4, odd)
#define SH_STRIDE  68          // own h:   [8 b][64 d]
#define SVH_STRIDE 260         // full Vh: [8 b][256 r]

#define SV_ELEMS   (256*SV_STRIDE)   // 17408
#define SU_ELEMS   (64*SU_STRIDE)    // 16640
#define SH_ELEMS   (8*SH_STRIDE)     // 544
#define SVH_ELEMS  (8*SVH_STRIDE)    // 2080
#define SRED_ELEMS 8192
#define SMEM_FLOATS (SV_ELEMS+SU_ELEMS+SH_ELEMS+SVH_ELEMS+SRED_ELEMS)
#define SMEM_BYTES  (SMEM_FLOATS*4)  // 179456 B < 227KB

// ---------------- device scratch (static, allocation-rule-safe) ----------------
__device__ float    g_wx[(size_t)T_STEPS*BATCH*DIM];   // Wx + bias, [t][b][d]
__device__ float    g_vh3[3*NSLOTS*BATCH*RANK];        // triple-buffered Vh accum [buf][s][b][r]
__device__ unsigned g_bar[NSLOTS];                     // per-slot monotonic barrier (fallback path)

// packed fp32x2 FMA (full-rate fp32 on sm_103a; 3-reg FFMA is half rate)
__device__ __forceinline__ float2 ffma2(float2 a, float2 b, float2 c) {
    float2 d;
    asm("fma.rn.f32x2 %0, %1, %2, %3;"
        : "=l"(*reinterpret_cast<unsigned long long*>(&d))
        : "l"(*reinterpret_cast<const unsigned long long*>(&a)),
          "l"(*reinterpret_cast<const unsigned long long*>(&b)),
          "l"(*reinterpret_cast<const unsigned long long*>(&c)));
    return d;
}
__device__ __forceinline__ float2 lo2(float4 v) { return make_float2(v.x, v.y); }
__device__ __forceinline__ float2 hi2(float4 v) { return make_float2(v.z, v.w); }

// ======================= kernel 1: Wx = x @ W^T + bias =======================
__global__ __launch_bounds__(256) void wx_kernel(const float* __restrict__ x,
                                                 const float* __restrict__ W,
                                                 const float* __restrict__ bias) {
    __shared__ float sA[64*36];
    __shared__ float sB[64*36];
    const int tid = threadIdx.x;
    const int m0 = blockIdx.y * 64;
    const int n0 = blockIdx.x * 64;
    if (blockIdx.x == 0 && blockIdx.y == 0 && tid < NSLOTS) g_bar[tid] = 0u;
    if (blockIdx.y == 0) {                // 16 CTAs x 256 thr zero the Vh buffers
        int base = blockIdx.x * 256 + tid;   // 0..4095
        #pragma unroll
        for (int k = 0; k < 12; k++) g_vh3[base + k*4096] = 0.f;
    }

    const int tm = tid >> 4;
    const int tn = tid & 15;

    float2 acc[4][4];
    #pragma unroll
    for (int i = 0; i < 4; i++)
        #pragma unroll
        for (int j = 0; j < 4; j++) acc[i][j] = make_float2(0.f, 0.f);

    for (int kb = 0; kb < 1024; kb += 32) {
        __syncthreads();
        #pragma unroll
        for (int it = 0; it < 2; it++) {
            int i = tid + it*256;
            int row = i >> 3, c4 = (i & 7) * 4;
            *(float4*)&sA[row*36 + c4] = *(const float4*)&x[(size_t)(m0+row)*1024 + kb + c4];
            *(float4*)&sB[row*36 + c4] = *(const float4*)&W[(size_t)(n0+row)*1024 + kb + c4];
        }
        __syncthreads();
        #pragma unroll
        for (int kk = 0; kk < 32; kk += 4) {
            float4 a[4], b[4];
            #pragma unroll
            for (int i = 0; i < 4; i++) a[i] = *(float4*)&sA[(tm+16*i)*36 + kk];
            #pragma unroll
            for (int j = 0; j < 4; j++) b[j] = *(float4*)&sB[(tn+16*j)*36 + kk];
            #pragma unroll
            for (int i = 0; i < 4; i++)
                #pragma unroll
                for (int j = 0; j < 4; j++) {
                    acc[i][j] = ffma2(lo2(a[i]), lo2(b[j]), acc[i][j]);
                    acc[i][j] = ffma2(hi2(a[i]), hi2(b[j]), acc[i][j]);
                }
        }
    }
    #pragma unroll
    for (int i = 0; i < 4; i++) {
        int m = m0 + tm + 16*i;
        #pragma unroll
        for (int j = 0; j < 4; j++) {
            int n = n0 + tn + 16*j;
            g_wx[(size_t)m*1024 + n] = acc[i][j].x + acc[i][j].y + bias[n];
        }
    }
}

// ================== kernel 2: persistent recurrence (d-partitioned) ==================
// 128 CTAs = 8 slots x 16 d-chunks, 512 threads each. CTA owns d in [dlo,dlo+64);
// its h slice never leaves SMEM. Partial Vh summed across the slot group via
// RED.F32 into a triple-buffered L2 staging area; one cluster barrier per step.
template <bool USE_CLUSTER>
__global__ void __launch_bounds__(NTHR, 1)
recur_kernel_t(const float* __restrict__ h0, const float* __restrict__ U,
               const float* __restrict__ V, float* __restrict__ hout) {
    extern __shared__ float sm[];
    float* sV   = sm;                    // [256][SV_STRIDE]  V[s][r][dlo+dd]
    float* sU   = sV  + SV_ELEMS;        // [64][SU_STRIDE]   U[s][dlo+di][r]
    float* sH   = sU  + SU_ELEMS;        // [8][SH_STRIDE]    own h[b][dlo+dd]
    float* sVh  = sH  + SH_ELEMS;        // [8][SVH_STRIDE]   summed Vh[b][r]
    float* sRed = sVh + SVH_ELEMS;       // 8192 floats scratch

    const int tid = threadIdx.x;
    const int s   = blockIdx.x >> 4;
    const int rk  = blockIdx.x & 15;
    const int dlo = rk * 64;

    // resident weights (float4): V[:, dlo:dlo+64] as [r][dd], U[dlo:dlo+64, :] as [di][r]
    #pragma unroll
    for (int k = 0; k < 8; k++) {           // 4096 float4: V chunk (256 rows x 16 f4)
        int i = tid + k*NTHR;
        int row = i >> 4, c4 = (i & 15) * 4;
        *(float4*)&sV[row*SV_STRIDE + c4] =
            *(const float4*)&V[((size_t)(s*256 + row))*1024 + dlo + c4];
    }
    #pragma unroll
    for (int k = 0; k < 8; k++) {           // 4096 float4: U chunk (64 rows x 64 f4)
        int i = tid + k*NTHR;
        int row = i >> 6, c4 = (i & 63) * 4;
        *(float4*)&sU[row*SU_STRIDE + c4] =
            *(const float4*)&U[((size_t)(s*1024 + dlo + row))*256 + c4];
    }
    // own h0 slice -> sH, and publish h[0] to output (512 values, one per thread)
    {
        int b = tid >> 6, dd = tid & 63;
        float v = h0[(size_t)b*8192 + s*1024 + dlo + dd];
        sH[b*SH_STRIDE + dd] = v;
        hout[(size_t)s*8192 + b*1024 + dlo + dd] = v;
    }

    // GEMM1 map: 128 r-threads (r, r+128) x 4 d-slices of 16
    const int rt1 = tid & 127;
    const int sl1 = tid >> 7;            // 0..3
    const int dbase1 = sl1 * 16;
    // GEMM2 map: 32 d-threads (d, d+32) x 16 r-slices of 16
    const int dt2 = tid & 31;
    const int sl2 = tid >> 5;            // 0..15
    const int rbase2 = sl2 * 16;
    // epilogue / prefetch map: one (b,d) per thread
    const int eb  = tid >> 6;
    const int edi = tid & 63;

    for (int t = 0; t < T_STEPS; t++) {
        // prefetch this step's Wx value (hides L2/DRAM latency behind GEMM1)
        float wxp = g_wx[(size_t)t*8192 + eb*1024 + dlo + edi];

        __syncthreads();   // sH ready from previous iteration's epilogue

        // ---- GEMM1: partial Vh[r][b] over own d-chunk (float4 over d) ----
        {
            float2 acc[2][8];
            #pragma unroll
            for (int i = 0; i < 2; i++)
                #pragma unroll
                for (int b = 0; b < 8; b++) acc[i][b] = make_float2(0.f, 0.f);
            #pragma unroll
            for (int dd = 0; dd < 16; dd += 4) {
                int d = dbase1 + dd;
                float4 v0 = *(float4*)&sV[rt1*SV_STRIDE + d];
                float4 v1 = *(float4*)&sV[(rt1+128)*SV_STRIDE + d];
                #pragma unroll
                for (int b = 0; b < 8; b++) {
                    float4 hh = *(float4*)&sH[b*SH_STRIDE + d];   // broadcast
                    acc[0][b] = ffma2(lo2(v0), lo2(hh), acc[0][b]);
                    acc[0][b] = ffma2(hi2(v0), hi2(hh), acc[0][b]);
                    acc[1][b] = ffma2(lo2(v1), lo2(hh), acc[1][b]);
                    acc[1][b] = ffma2(hi2(v1), hi2(hh), acc[1][b]);
                }
            }
            #pragma unroll
            for (int i = 0; i < 2; i++)
                #pragma unroll
                for (int b = 0; b < 8; b++)
                    sRed[sl1*2048 + b*256 + rt1 + 128*i] = acc[i][b].x + acc[i][b].y;
        }
        __syncthreads();

        // combine 4 d-slices + RED-publish into g_vh3[t%3][s] (layout [b][r])
        float* gbuf = g_vh3 + ((size_t)(t % 3) * NSLOTS + s) * 2048;
        #pragma unroll
        for (int k = 0; k < 4; k++) {
            int idx = tid + k*NTHR;     // (b*256 + r), 2048 total
            float v = sRed[idx] + sRed[2048 + idx] + sRed[4096 + idx] + sRed[6144 + idx];
            atomicAdd(&gbuf[idx], v);   // REDG, no return
        }

        // ---- ONE barrier per step (per slot group) ----
        if (USE_CLUSTER) {
            asm volatile("barrier.cluster.arrive.aligned;" ::: "memory");
            asm volatile("barrier.cluster.wait.aligned;"   ::: "memory");
        } else {
            __threadfence();
            __syncthreads();
            if (tid == 0) {
                atomicAdd(&g_bar[s], 1u);
                unsigned target = (unsigned)GROUP * (unsigned)(t + 1);
                while (*((volatile unsigned*)&g_bar[s]) < target) { }
            }
            __syncthreads();
        }

        // stage summed Vh (L2, bypass L1), zero the buffer for step t+2
        {
            float4 v = __ldcg(&((const float4*)gbuf)[tid]);   // 512 float4
            int b = tid >> 6, c4 = (tid & 63) * 4;
            *(float4*)&sVh[b*SVH_STRIDE + c4] = v;
            float* zbuf = g_vh3 + ((size_t)((t + 2) % 3) * NSLOTS + s) * 2048;
            if (tid < 128) zbuf[rk*128 + tid] = 0.f;
        }
        __syncthreads();

        // ---- GEMM2: Uh[d][b] = sum_r U[d][r]*Vh[b][r] (float4 over r) ----
        {
            float2 acc[2][8];
            #pragma unroll
            for (int i = 0; i < 2; i++)
                #pragma unroll
                for (int b = 0; b < 8; b++) acc[i][b] = make_float2(0.f, 0.f);
            #pragma unroll
            for (int rr = 0; rr < 16; rr += 4) {
                int r = rbase2 + rr;
                float4 u0 = *(float4*)&sU[dt2*SU_STRIDE + r];
                float4 u1 = *(float4*)&sU[(dt2+32)*SU_STRIDE + r];
                #pragma unroll
                for (int b = 0; b < 8; b++) {
                    float4 vh = *(float4*)&sVh[b*SVH_STRIDE + r];  // broadcast
                    acc[0][b] = ffma2(lo2(u0), lo2(vh), acc[0][b]);
                    acc[0][b] = ffma2(hi2(u0), hi2(vh), acc[0][b]);
                    acc[1][b] = ffma2(lo2(u1), lo2(vh), acc[1][b]);
                    acc[1][b] = ffma2(hi2(u1), hi2(vh), acc[1][b]);
                }
            }
            #pragma unroll
            for (int i = 0; i < 2; i++)
                #pragma unroll
                for (int b = 0; b < 8; b++)
                    sRed[sl2*512 + b*64 + dt2 + 32*i] = acc[i][b].x + acc[i][b].y;
        }
        __syncthreads();

        // epilogue: h_new = tanh(Wx + Uh); keep slice in sH, publish to hout
        {
            float uh = 0.f;
            #pragma unroll
            for (int k = 0; k < 16; k++) uh += sRed[k*512 + tid];
            float hn = tanhf(wxp + uh);
            sH[eb*SH_STRIDE + edi] = hn;
            hout[((size_t)(t+1)*8 + s)*8192 + eb*1024 + dlo + edi] = hn;
        }
    }
}

// ============== kernel 3: out = (sum_s C_s h[t+1,s]) * silu(z) ==============
__global__ __launch_bounds__(256) void out_kernel(const float* __restrict__ z,
                                                  const float* __restrict__ C,
                                                  const float* __restrict__ hout,
                                                  float* __restrict__ out) {
    size_t idx = (size_t)blockIdx.x * 256 + threadIdx.x;   // < T*B*D exactly
    int t   = (int)(idx >> 13);
    int rem = (int)(idx & 8191);
    float zz  = z[idx];
    float sig = 1.f / (1.f + expf(-zz));
    const float* hb = hout + ((size_t)(t+1))*65536 + rem;
    float acc = 0.f;
    #pragma unroll
    for (int s = 0; s < 8; s++) acc += C[s] * hb[(size_t)s*8192];
    out[idx] = acc * zz * sig;
}

// ================================ launch ================================
extern "C" void kernel_launch(void* const* d_in, const int* in_sizes, int n_in,
                              void* d_out, int out_size) {
    (void)in_sizes; (void)n_in; (void)out_size;
    const float* x    = (const float*)d_in[0];
    const float* z    = (const float*)d_in[1];
    const float* h0   = (const float*)d_in[2];
    const float* Wxm  = (const float*)d_in[3];
    const float* U    = (const float*)d_in[4];
    const float* V    = (const float*)d_in[5];
    const float* bias = (const float*)d_in[6];
    const float* C    = (const float*)d_in[7];

    float* out  = (float*)d_out;
    float* hout = out + (size_t)T_STEPS*BATCH*DIM;   // h region: [T+1][S][B][D]

    cudaFuncSetAttribute(recur_kernel_t<true>,
                         cudaFuncAttributeMaxDynamicSharedMemorySize, SMEM_BYTES);
    cudaFuncSetAttribute(recur_kernel_t<true>,
                         cudaFuncAttributeNonPortableClusterSizeAllowed, 1);
    cudaFuncSetAttribute(recur_kernel_t<false>,
                         cudaFuncAttributeMaxDynamicSharedMemorySize, SMEM_BYTES);

    dim3 wgrid(16, 128);
    wx_kernel<<<wgrid, 256>>>(x, Wxm, bias);

    // cluster launch config: 8 clusters x 16 CTAs (slot group == cluster)
    cudaLaunchConfig_t cfg = {};
    cfg.gridDim          = dim3(NCTAS, 1, 1);
    cfg.blockDim         = dim3(NTHR, 1, 1);
    cfg.dynamicSmemBytes = SMEM_BYTES;
    cudaLaunchAttribute attrs[1];
    attrs[0].id = cudaLaunchAttributeClusterDimension;
    attrs[0].val.clusterDim.x = GROUP;
    attrs[0].val.clusterDim.y = 1;
    attrs[0].val.clusterDim.z = 1;
    cfg.attrs    = attrs;
    cfg.numAttrs = 1;

    int maxClusters = 0;
    cudaError_t qe = cudaOccupancyMaxActiveClusters(&maxClusters,
                                                    recur_kernel_t<true>, &cfg);
    bool use_cluster = (qe == cudaSuccess && maxClusters >= NSLOTS);
    if (!use_cluster) (void)cudaGetLastError();   // clear any query error

    if (use_cluster) {
        cudaError_t le = cudaLaunchKernelEx(&cfg, recur_kernel_t<true>,
                                            h0, U, V, hout);
        if (le != cudaSuccess) {
            (void)cudaGetLastError();
            use_cluster = false;
        }
    }
    if (!use_cluster) {
        recur_kernel_t<false><<<NCTAS, NTHR, SMEM_BYTES>>>(h0, U, V, hout);
    }

    out_kernel<<<32768, 256>>>(z, C, hout, out);
}

// round 9
// speedup vs baseline: 1.0950x; 1.0950x over previous
#include <cuda_runtime.h>
#include <cstdint>
#include <cstddef>

#define T_STEPS 1024
#define BATCH   8
#define DIM     1024
#define NSLOTS  8
#define RANK    256
#define GROUP   16            // CTAs per slot group (= cluster size)
#define NCTAS   (NSLOTS*GROUP)

// SMEM strides (floats): odd multiples of 4 floats (16B) => 16B-aligned rows
// AND conflict-free LDS.128 column access (stride/4 mod 8 == 1).
#define SV_STRIDE  68          // V chunk: [256 r][64 d]   (17 float4)
#define SU_STRIDE  260         // U chunk: [64 d][256 r]   (65 float4)
#define SH_STRIDE  68          // own h:   [8 b][64 d]
#define SVH_STRIDE 260         // full Vh: [8 b][256 r]

#define SV_ELEMS   (256*SV_STRIDE)   // 17408
#define SU_ELEMS   (64*SU_STRIDE)    // 16640
#define SH_ELEMS   (8*SH_STRIDE)     // 544
#define SVH_ELEMS  (8*SVH_STRIDE)    // 2080
#define SRED_ELEMS 4096
#define SMEM_FLOATS (SV_ELEMS+SU_ELEMS+SH_ELEMS+SVH_ELEMS+SRED_ELEMS)
#define SMEM_BYTES  (SMEM_FLOATS*4)  // 163072 B < 227KB

// ---------------- device scratch (static, allocation-rule-safe) ----------------
__device__ float    g_wx[(size_t)T_STEPS*BATCH*DIM];   // Wx + bias, [t][b][d]
__device__ float    g_vh3[3*NSLOTS*BATCH*RANK];        // triple-buffered Vh accum [buf][s][b][r]
__device__ unsigned g_bar[NSLOTS];                     // per-slot monotonic barrier (fallback path)

// packed fp32x2 FMA (full-rate fp32 on sm_103a; 3-reg FFMA is half rate)
__device__ __forceinline__ float2 ffma2(float2 a, float2 b, float2 c) {
    float2 d;
    asm("fma.rn.f32x2 %0, %1, %2, %3;"
        : "=l"(*reinterpret_cast<unsigned long long*>(&d))
        : "l"(*reinterpret_cast<const unsigned long long*>(&a)),
          "l"(*reinterpret_cast<const unsigned long long*>(&b)),
          "l"(*reinterpret_cast<const unsigned long long*>(&c)));
    return d;
}
__device__ __forceinline__ float2 lo2(float4 v) { return make_float2(v.x, v.y); }
__device__ __forceinline__ float2 hi2(float4 v) { return make_float2(v.z, v.w); }

// ======================= kernel 1: Wx = x @ W^T + bias =======================
__global__ __launch_bounds__(256) void wx_kernel(const float* __restrict__ x,
                                                 const float* __restrict__ W,
                                                 const float* __restrict__ bias) {
    __shared__ float sA[64*36];
    __shared__ float sB[64*36];
    const int tid = threadIdx.x;
    const int m0 = blockIdx.y * 64;
    const int n0 = blockIdx.x * 64;
    if (blockIdx.x == 0 && blockIdx.y == 0 && tid < NSLOTS) g_bar[tid] = 0u;
    if (blockIdx.y == 0) {                // 16 CTAs x 256 thr zero the Vh buffers
        int base = blockIdx.x * 256 + tid;   // 0..4095
        #pragma unroll
        for (int k = 0; k < 12; k++) g_vh3[base + k*4096] = 0.f;
    }

    const int tm = tid >> 4;
    const int tn = tid & 15;

    float2 acc[4][4];
    #pragma unroll
    for (int i = 0; i < 4; i++)
        #pragma unroll
        for (int j = 0; j < 4; j++) acc[i][j] = make_float2(0.f, 0.f);

    for (int kb = 0; kb < 1024; kb += 32) {
        __syncthreads();
        #pragma unroll
        for (int it = 0; it < 2; it++) {
            int i = tid + it*256;
            int row = i >> 3, c4 = (i & 7) * 4;
            *(float4*)&sA[row*36 + c4] = *(const float4*)&x[(size_t)(m0+row)*1024 + kb + c4];
            *(float4*)&sB[row*36 + c4] = *(const float4*)&W[(size_t)(n0+row)*1024 + kb + c4];
        }
        __syncthreads();
        #pragma unroll
        for (int kk = 0; kk < 32; kk += 4) {
            float4 a[4], b[4];
            #pragma unroll
            for (int i = 0; i < 4; i++) a[i] = *(float4*)&sA[(tm+16*i)*36 + kk];
            #pragma unroll
            for (int j = 0; j < 4; j++) b[j] = *(float4*)&sB[(tn+16*j)*36 + kk];
            #pragma unroll
            for (int i = 0; i < 4; i++)
                #pragma unroll
                for (int j = 0; j < 4; j++) {
                    acc[i][j] = ffma2(lo2(a[i]), lo2(b[j]), acc[i][j]);
                    acc[i][j] = ffma2(hi2(a[i]), hi2(b[j]), acc[i][j]);
                }
        }
    }
    #pragma unroll
    for (int i = 0; i < 4; i++) {
        int m = m0 + tm + 16*i;
        #pragma unroll
        for (int j = 0; j < 4; j++) {
            int n = n0 + tn + 16*j;
            g_wx[(size_t)m*1024 + n] = acc[i][j].x + acc[i][j].y + bias[n];
        }
    }
}

// ================== kernel 2: persistent recurrence (d-partitioned) ==================
// 128 CTAs = 8 slots x 16 d-chunks, 256 threads each. CTA owns d in [dlo,dlo+64);
// its h slice never leaves SMEM. Partial Vh summed across the slot group via
// RED.F32 into a triple-buffered L2 staging area; one cluster barrier per step.
template <bool USE_CLUSTER>
__global__ void __launch_bounds__(256, 1)
recur_kernel_t(const float* __restrict__ h0, const float* __restrict__ U,
               const float* __restrict__ V, float* __restrict__ hout) {
    extern __shared__ float sm[];
    float* sV   = sm;                    // [256][SV_STRIDE]  V[s][r][dlo+dd]
    float* sU   = sV  + SV_ELEMS;        // [64][SU_STRIDE]   U[s][dlo+di][r]
    float* sH   = sU  + SU_ELEMS;        // [8][SH_STRIDE]    own h[b][dlo+dd]
    float* sVh  = sH  + SH_ELEMS;        // [8][SVH_STRIDE]   summed Vh[b][r]
    float* sRed = sVh + SVH_ELEMS;       // 4096 floats scratch

    const int tid = threadIdx.x;
    const int s   = blockIdx.x >> 4;
    const int rk  = blockIdx.x & 15;
    const int dlo = rk * 64;

    // resident weights (float4): V[:, dlo:dlo+64] as [r][dd], U[dlo:dlo+64, :] as [di][r]
    #pragma unroll
    for (int k = 0; k < 16; k++) {          // 4096 float4: V chunk (256 rows x 16 f4)
        int i = tid + k*256;
        int row = i >> 4, c4 = (i & 15) * 4;
        *(float4*)&sV[row*SV_STRIDE + c4] =
            *(const float4*)&V[((size_t)(s*256 + row))*1024 + dlo + c4];
    }
    #pragma unroll
    for (int k = 0; k < 16; k++) {          // 4096 float4: U chunk (64 rows x 64 f4)
        int i = tid + k*256;
        int row = i >> 6, c4 = (i & 63) * 4;
        *(float4*)&sU[row*SU_STRIDE + c4] =
            *(const float4*)&U[((size_t)(s*1024 + dlo + row))*256 + c4];
    }
    // own h0 slice -> sH, and publish h[0] to output
    for (int i = tid; i < 512; i += 256) {
        int b = i >> 6, dd = i & 63;
        float v = h0[(size_t)b*8192 + s*1024 + dlo + dd];
        sH[b*SH_STRIDE + dd] = v;
        hout[(size_t)s*8192 + b*1024 + dlo + dd] = v;
    }

    // GEMM1 map: 128 r-threads (r, r+128) x 2 d-halves of 32
    const int rt1 = tid & 127;
    const int dbase1 = (tid >> 7) * 32;
    const int ks1 = tid >> 7;
    // GEMM2 map: 32 d-threads (d, d+32) x 8 r-slices of 32
    const int dt2 = tid & 31;
    const int ks2 = tid >> 5;
    // epilogue map
    const int edi = tid & 63;
    const int eb  = tid >> 6;            // handles b=eb and b=eb+4

    for (int t = 0; t < T_STEPS; t++) {
        // prefetch this step's Wx values (hides L2/DRAM latency behind GEMM1)
        const float* wxrow = g_wx + (size_t)t * 8192;
        float wxp0 = wxrow[(eb    )*1024 + dlo + edi];
        float wxp1 = wxrow[(eb + 4)*1024 + dlo + edi];

        __syncthreads();   // sH/sRed ready from previous iteration

        // ---- GEMM1: partial Vh[r][b] over own d-chunk (float4 over d) ----
        {
            float2 acc[2][8];
            #pragma unroll
            for (int i = 0; i < 2; i++)
                #pragma unroll
                for (int b = 0; b < 8; b++) acc[i][b] = make_float2(0.f, 0.f);
            #pragma unroll
            for (int dd = 0; dd < 32; dd += 4) {
                int d = dbase1 + dd;
                float4 v0 = *(float4*)&sV[rt1*SV_STRIDE + d];
                float4 v1 = *(float4*)&sV[(rt1+128)*SV_STRIDE + d];
                #pragma unroll
                for (int b = 0; b < 8; b++) {
                    float4 hh = *(float4*)&sH[b*SH_STRIDE + d];   // broadcast
                    acc[0][b] = ffma2(lo2(v0), lo2(hh), acc[0][b]);
                    acc[0][b] = ffma2(hi2(v0), hi2(hh), acc[0][b]);
                    acc[1][b] = ffma2(lo2(v1), lo2(hh), acc[1][b]);
                    acc[1][b] = ffma2(hi2(v1), hi2(hh), acc[1][b]);
                }
            }
            #pragma unroll
            for (int i = 0; i < 2; i++)
                #pragma unroll
                for (int b = 0; b < 8; b++)
                    sRed[ks1*2048 + b*256 + rt1 + 128*i] = acc[i][b].x + acc[i][b].y;
        }
        __syncthreads();

        // combine d-halves + RED-publish into g_vh3[t%3][s] (layout [b][r])
        float* gbuf = g_vh3 + ((size_t)(t % 3) * NSLOTS + s) * 2048;
        {
            int r = tid;   // 0..255
            #pragma unroll
            for (int b = 0; b < 8; b++) {
                float v = sRed[b*256 + r] + sRed[2048 + b*256 + r];
                atomicAdd(&gbuf[b*256 + r], v);   // REDG, no return
            }
        }

        // ---- ONE barrier per step (per slot group) ----
        if (USE_CLUSTER) {
            // arrive = cluster-scope release (orders the REDs above);
            // wait   = cluster-scope acquire (orders the ldcg reads below).
            asm volatile("barrier.cluster.arrive.aligned;" ::: "memory");
            asm volatile("barrier.cluster.wait.aligned;"   ::: "memory");
        } else {
            __threadfence();
            __syncthreads();
            if (tid == 0) {
                atomicAdd(&g_bar[s], 1u);
                unsigned target = (unsigned)GROUP * (unsigned)(t + 1);
                while (*((volatile unsigned*)&g_bar[s]) < target) { }
            }
            __syncthreads();
        }

        // stage summed Vh (L2, bypass L1) and zero the buffer for step t+2
        {
            const float4* src = (const float4*)gbuf;
            #pragma unroll
            for (int k = 0; k < 2; k++) {
                int i = tid + k*256;                // 512 float4
                float4 v = __ldcg(&src[i]);
                int b = i >> 6, c4 = (i & 63) * 4;
                *(float4*)&sVh[b*SVH_STRIDE + c4] = v;
            }
            float* zbuf = g_vh3 + ((size_t)((t + 2) % 3) * NSLOTS + s) * 2048;
            if (tid < 128) zbuf[rk*128 + tid] = 0.f;
        }
        __syncthreads();

        // ---- GEMM2: Uh[d][b] = sum_r U[d][r]*Vh[b][r] (float4 over r) ----
        {
            float2 acc[2][8];
            #pragma unroll
            for (int i = 0; i < 2; i++)
                #pragma unroll
                for (int b = 0; b < 8; b++) acc[i][b] = make_float2(0.f, 0.f);
            const int rbase = ks2 * 32;
            #pragma unroll
            for (int rr = 0; rr < 32; rr += 4) {
                int r = rbase + rr;
                float4 u0 = *(float4*)&sU[dt2*SU_STRIDE + r];
                float4 u1 = *(float4*)&sU[(dt2+32)*SU_STRIDE + r];
                #pragma unroll
                for (int b = 0; b < 8; b++) {
                    float4 vh = *(float4*)&sVh[b*SVH_STRIDE + r];  // broadcast
                    acc[0][b] = ffma2(lo2(u0), lo2(vh), acc[0][b]);
                    acc[0][b] = ffma2(hi2(u0), hi2(vh), acc[0][b]);
                    acc[1][b] = ffma2(lo2(u1), lo2(vh), acc[1][b]);
                    acc[1][b] = ffma2(hi2(u1), hi2(vh), acc[1][b]);
                }
            }
            #pragma unroll
            for (int i = 0; i < 2; i++)
                #pragma unroll
                for (int b = 0; b < 8; b++)
                    sRed[ks2*512 + b*64 + dt2 + 32*i] = acc[i][b].x + acc[i][b].y;
        }
        __syncthreads();

        // epilogue: h_new = tanh(Wx + Uh); keep slice in sH, publish to hout
        {
            float* hdst = hout + ((size_t)(t+1)*8 + s)*8192;
            #pragma unroll
            for (int j = 0; j < 2; j++) {
                int b = eb + 4*j;
                float uh = 0.f;
                #pragma unroll
                for (int k = 0; k < 8; k++) uh += sRed[k*512 + b*64 + edi];
                float hn = tanhf((j == 0 ? wxp0 : wxp1) + uh);
                sH[b*SH_STRIDE + edi] = hn;
                hdst[b*1024 + dlo + edi] = hn;
            }
        }
    }
}

// ============== kernel 3: out = (sum_s C_s h[t+1,s]) * silu(z) ==============
__global__ __launch_bounds__(256) void out_kernel(const float* __restrict__ z,
                                                  const float* __restrict__ C,
                                                  const float* __restrict__ hout,
                                                  float* __restrict__ out) {
    size_t idx = (size_t)blockIdx.x * 256 + threadIdx.x;   // < T*B*D exactly
    int t   = (int)(idx >> 13);
    int rem = (int)(idx & 8191);
    float zz  = z[idx];
    float sig = 1.f / (1.f + expf(-zz));
    const float* hb = hout + ((size_t)(t+1))*65536 + rem;
    float acc = 0.f;
    #pragma unroll
    for (int s = 0; s < 8; s++) acc += C[s] * hb[(size_t)s*8192];
    out[idx] = acc * zz * sig;
}

// ================================ launch ================================
extern "C" void kernel_launch(void* const* d_in, const int* in_sizes, int n_in,
                              void* d_out, int out_size) {
    (void)in_sizes; (void)n_in; (void)out_size;
    const float* x    = (const float*)d_in[0];
    const float* z    = (const float*)d_in[1];
    const float* h0   = (const float*)d_in[2];
    const float* Wxm  = (const float*)d_in[3];
    const float* U    = (const float*)d_in[4];
    const float* V    = (const float*)d_in[5];
    const float* bias = (const float*)d_in[6];
    const float* C    = (const float*)d_in[7];

    float* out  = (float*)d_out;
    float* hout = out + (size_t)T_STEPS*BATCH*DIM;   // h region: [T+1][S][B][D]

    cudaFuncSetAttribute(recur_kernel_t<true>,
                         cudaFuncAttributeMaxDynamicSharedMemorySize, SMEM_BYTES);
    cudaFuncSetAttribute(recur_kernel_t<true>,
                         cudaFuncAttributeNonPortableClusterSizeAllowed, 1);
    cudaFuncSetAttribute(recur_kernel_t<false>,
                         cudaFuncAttributeMaxDynamicSharedMemorySize, SMEM_BYTES);

    dim3 wgrid(16, 128);
    wx_kernel<<<wgrid, 256>>>(x, Wxm, bias);

    // cluster launch config: 8 clusters x 16 CTAs (slot group == cluster)
    cudaLaunchConfig_t cfg = {};
    cfg.gridDim          = dim3(NCTAS, 1, 1);
    cfg.blockDim         = dim3(256, 1, 1);
    cfg.dynamicSmemBytes = SMEM_BYTES;
    cudaLaunchAttribute attrs[1];
    attrs[0].id = cudaLaunchAttributeClusterDimension;
    attrs[0].val.clusterDim.x = GROUP;
    attrs[0].val.clusterDim.y = 1;
    attrs[0].val.clusterDim.z = 1;
    cfg.attrs    = attrs;
    cfg.numAttrs = 1;

    int maxClusters = 0;
    cudaError_t qe = cudaOccupancyMaxActiveClusters(&maxClusters,
                                                    recur_kernel_t<true>, &cfg);
    bool use_cluster = (qe == cudaSuccess && maxClusters >= NSLOTS);
    if (!use_cluster) (void)cudaGetLastError();   // clear any query error

    if (use_cluster) {
        cudaError_t le = cudaLaunchKernelEx(&cfg, recur_kernel_t<true>,
                                            h0, U, V, hout);
        if (le != cudaSuccess) {
            (void)cudaGetLastError();
            use_cluster = false;
        }
    }
    if (!use_cluster) {
        recur_kernel_t<false><<<NCTAS, 256, SMEM_BYTES>>>(h0, U, V, hout);
    }

    out_kernel<<<32768, 256>>>(z, C, hout, out);
}